// round 1
// baseline (speedup 1.0000x reference)
#include <cuda_runtime.h>
#include <cuda_bf16.h>
#include <math.h>

// Problem constants (shapes fixed by the dataset; N/E re-derived from in_sizes)
#define MAXN 100000
#define IN_SIZE 256
#define OUT_SIZE 64

// Scratch (device globals; no allocation allowed in kernel_launch)
__device__ __align__(256) float g_xw[MAXN * OUT_SIZE];   // X @ W^T
__device__ __align__(256) float g_dinv[MAXN];            // D^{-1/2}
__device__ __align__(256) int   g_deg[MAXN];             // non-self-edge counts

// ---------------------------------------------------------------------------
// 1) zero degree counters
__global__ void k_zero_deg(int N) {
    int i = blockIdx.x * blockDim.x + threadIdx.x;
    if (i < N) g_deg[i] = 0;
}

// 2) count non-self edges per row
__global__ void k_count(const int* __restrict__ ei, int E) {
    int e = blockIdx.x * blockDim.x + threadIdx.x;
    if (e < E) {
        int r = ei[e];
        int c = ei[E + e];
        if (r != c) atomicAdd(&g_deg[r], 1);
    }
}

// 3) dinv = (deg + 1)^{-1/2}  (the +1 is the mandatory self loop, so deg>0 always)
__global__ void k_dinv(int N) {
    int i = blockIdx.x * blockDim.x + threadIdx.x;
    if (i < N) g_dinv[i] = rsqrtf((float)(g_deg[i] + 1));
}

// ---------------------------------------------------------------------------
// 4) GEMM: g_xw[N,64] = x[N,256] @ W[64,256]^T   (fp32, tiled)
//    Block tile: 64 rows x 64 cols, BK=32. 256 threads as 16x16, 4x4 per thread.
#define BM 64
#define BN 64
#define BK 32

__global__ __launch_bounds__(256) void k_gemm(const float* __restrict__ x,
                                              const float* __restrict__ W,
                                              int N) {
    __shared__ float As[BK][BM + 4];
    __shared__ float Bs[BK][BN + 4];

    int tid = threadIdx.x;
    int tr = tid >> 4;          // 0..15 (row group)
    int tc = tid & 15;          // 0..15 (col group)
    int m0 = blockIdx.x * BM;

    float acc[4][4];
#pragma unroll
    for (int i = 0; i < 4; i++)
#pragma unroll
        for (int j = 0; j < 4; j++) acc[i][j] = 0.0f;

    for (int k0 = 0; k0 < IN_SIZE; k0 += BK) {
        // load x tile: 64 rows x 32 k  (8 float4 slots per row, 512 slots, 256 thr)
#pragma unroll
        for (int it = 0; it < 2; it++) {
            int idx = tid + it * 256;       // 0..511
            int r   = idx >> 3;             // 0..63
            int kk  = (idx & 7) * 4;        // 0,4,...,28
            float4 v = make_float4(0.f, 0.f, 0.f, 0.f);
            int gr = m0 + r;
            if (gr < N)
                v = *reinterpret_cast<const float4*>(&x[(size_t)gr * IN_SIZE + k0 + kk]);
            As[kk + 0][r] = v.x;
            As[kk + 1][r] = v.y;
            As[kk + 2][r] = v.z;
            As[kk + 3][r] = v.w;
        }
        // load W tile: 64 rows(n) x 32 k
#pragma unroll
        for (int it = 0; it < 2; it++) {
            int idx = tid + it * 256;
            int n   = idx >> 3;
            int kk  = (idx & 7) * 4;
            float4 v = *reinterpret_cast<const float4*>(&W[(size_t)n * IN_SIZE + k0 + kk]);
            Bs[kk + 0][n] = v.x;
            Bs[kk + 1][n] = v.y;
            Bs[kk + 2][n] = v.z;
            Bs[kk + 3][n] = v.w;
        }
        __syncthreads();

#pragma unroll
        for (int kk = 0; kk < BK; kk++) {
            float4 a4 = *reinterpret_cast<const float4*>(&As[kk][tr * 4]);
            float4 b4 = *reinterpret_cast<const float4*>(&Bs[kk][tc * 4]);
            float a[4] = {a4.x, a4.y, a4.z, a4.w};
            float b[4] = {b4.x, b4.y, b4.z, b4.w};
#pragma unroll
            for (int i = 0; i < 4; i++)
#pragma unroll
                for (int j = 0; j < 4; j++) acc[i][j] = fmaf(a[i], b[j], acc[i][j]);
        }
        __syncthreads();
    }

    // store 4x4 tile
#pragma unroll
    for (int i = 0; i < 4; i++) {
        int gr = m0 + tr * 4 + i;
        if (gr < N) {
            float4 v = make_float4(acc[i][0], acc[i][1], acc[i][2], acc[i][3]);
            *reinterpret_cast<float4*>(&g_xw[(size_t)gr * OUT_SIZE + tc * 4]) = v;
        }
    }
}

// ---------------------------------------------------------------------------
// 5) init output with self-loop term: out[i,:] = dinv[i]^2 * xw[i,:]
__global__ void k_selfloop(float* __restrict__ out, int N) {
    int i = blockIdx.x * blockDim.x + threadIdx.x;  // over N*OUT_SIZE
    if (i < N * OUT_SIZE) {
        int n = i >> 6;
        float d = g_dinv[n];
        out[i] = d * d * g_xw[i];
    }
}

// 6) edge aggregation: out[row,:] += dinv[row]*dinv[col]*xw[col,:]
//    16 threads per edge, one red.global.add.v4.f32 each (4 floats).
__global__ __launch_bounds__(256) void k_agg(const int* __restrict__ ei,
                                             float* __restrict__ out,
                                             int E) {
    long long gid = (long long)blockIdx.x * blockDim.x + threadIdx.x;
    int e  = (int)(gid >> 4);
    int cc = (int)(gid & 15);
    if (e < E) {
        int r = ei[e];
        int c = ei[E + e];
        if (r != c) {
            float s = g_dinv[r] * g_dinv[c];
            float4 v = *reinterpret_cast<const float4*>(&g_xw[(size_t)c * OUT_SIZE + cc * 4]);
            float* dst = out + (size_t)r * OUT_SIZE + cc * 4;
            asm volatile(
                "red.global.add.v4.f32 [%0], {%1, %2, %3, %4};"
                :: "l"(dst), "f"(v.x * s), "f"(v.y * s), "f"(v.z * s), "f"(v.w * s)
                : "memory");
        }
    }
}

// ---------------------------------------------------------------------------
extern "C" void kernel_launch(void* const* d_in, const int* in_sizes, int n_in,
                              void* d_out, int out_size) {
    const int*   ei = (const int*)d_in[0];     // [2, E]
    const float* x  = (const float*)d_in[1];   // [N, 256]
    // d_in[2] = num_nodes (scalar, unused; derived from sizes)
    const float* W  = (const float*)d_in[3];   // [64, 256]
    float* out = (float*)d_out;

    int E = in_sizes[0] / 2;
    int N = in_sizes[1] / IN_SIZE;

    k_zero_deg<<<(N + 255) / 256, 256>>>(N);
    k_count<<<(E + 255) / 256, 256>>>(ei, E);
    k_dinv<<<(N + 255) / 256, 256>>>(N);
    k_gemm<<<(N + BM - 1) / BM, 256>>>(x, W, N);
    k_selfloop<<<(N * OUT_SIZE + 255) / 256, 256>>>(out, N);
    {
        long long total = (long long)E * 16;
        int blocks = (int)((total + 255) / 256);
        k_agg<<<blocks, 256>>>(ei, out, E);
    }
}

// round 3
// speedup vs baseline: 1.6112x; 1.6112x over previous
#include <cuda_runtime.h>
#include <math.h>
#include <stdint.h>

#define MAXN 100000
#define MAXE 1600000
#define IN_SIZE 256
#define OUT_SIZE 64

// ---------------- device scratch (no allocation allowed) ----------------
__device__ __align__(256) float    g_xw[MAXN * OUT_SIZE];       // X @ W^T
__device__ __align__(256) uint32_t g_wt[IN_SIZE * OUT_SIZE];    // W^T in tf32, [k][n]
__device__ __align__(256) float    g_dinv[MAXN];                // D^{-1/2}
__device__ __align__(256) int      g_deg[MAXN];                 // non-self degree
__device__ __align__(256) int      g_rowstart[MAXN];            // CSR row offsets
__device__ __align__(256) int      g_bsum[256];
__device__ __align__(256) int      g_boff[256];
__device__ __align__(256) int      g_slot[MAXE];                // per-edge slot in row
__device__ __align__(256) int      g_col[MAXE];                 // CSR column indices

__device__ __forceinline__ uint32_t f2tf(float f) {
    uint32_t r;
    asm("cvt.rna.tf32.f32 %0, %1;" : "=r"(r) : "f"(f));
    return r;
}

// ---------------- degree / dinv ----------------
__global__ void k_zero_deg(int N) {
    int i = blockIdx.x * blockDim.x + threadIdx.x;
    if (i < N) g_deg[i] = 0;
}

__global__ void k_count(const int* __restrict__ ei, int E) {
    int e = blockIdx.x * blockDim.x + threadIdx.x;
    if (e < E) {
        int r = ei[e];
        int c = ei[E + e];
        if (r != c) g_slot[e] = atomicAdd(&g_deg[r], 1);
    }
}

__global__ void k_dinv(int N) {
    int i = blockIdx.x * blockDim.x + threadIdx.x;
    if (i < N) g_dinv[i] = rsqrtf((float)(g_deg[i] + 1));   // +1: self loop
}

// ---------------- 2-level exclusive scan of g_deg -> g_rowstart ----------------
__global__ __launch_bounds__(1024) void k_scan1(int N) {
    __shared__ int s[1024];
    int i = blockIdx.x * 1024 + threadIdx.x;
    int v = (i < N) ? g_deg[i] : 0;
    s[threadIdx.x] = v;
    __syncthreads();
    for (int off = 1; off < 1024; off <<= 1) {
        int t = (threadIdx.x >= off) ? s[threadIdx.x - off] : 0;
        __syncthreads();
        s[threadIdx.x] += t;
        __syncthreads();
    }
    if (i < N) g_rowstart[i] = s[threadIdx.x] - v;          // exclusive
    if (threadIdx.x == 1023) g_bsum[blockIdx.x] = s[1023];
}

__global__ void k_scan2(int NB) {
    __shared__ int s[128];
    int v = (threadIdx.x < NB) ? g_bsum[threadIdx.x] : 0;
    s[threadIdx.x] = v;
    __syncthreads();
    for (int off = 1; off < 128; off <<= 1) {
        int t = (threadIdx.x >= off) ? s[threadIdx.x - off] : 0;
        __syncthreads();
        s[threadIdx.x] += t;
        __syncthreads();
    }
    if (threadIdx.x < NB) g_boff[threadIdx.x] = s[threadIdx.x] - v;
}

__global__ void k_scan3(int N) {
    int i = blockIdx.x * blockDim.x + threadIdx.x;
    if (i < N) g_rowstart[i] += g_boff[i >> 10];
}

__global__ void k_scatter(const int* __restrict__ ei, int E) {
    int e = blockIdx.x * blockDim.x + threadIdx.x;
    if (e < E) {
        int r = ei[e];
        int c = ei[E + e];
        if (r != c) g_col[g_rowstart[r] + g_slot[e]] = c;
    }
}

// ---------------- W transpose + tf32 convert ----------------
__global__ void k_wt(const float* __restrict__ W) {
    int i = blockIdx.x * blockDim.x + threadIdx.x;   // over 256*64
    if (i < IN_SIZE * OUT_SIZE) {
        int k = i >> 6;
        int n = i & 63;
        g_wt[i] = f2tf(W[n * IN_SIZE + k]);
    }
}

// ---------------- GEMM: g_xw[N,64] = x[N,256] @ W^T via tf32 mma ----------------
#define GM 128
#define GK 32
#define AS_STRIDE 36
#define WS_STRIDE 72

__global__ __launch_bounds__(256) void k_gemm(const float* __restrict__ x, int N) {
    __shared__ uint32_t s_a[GM * AS_STRIDE];   // 18432 B
    __shared__ uint32_t s_w[GK * WS_STRIDE];   //  9216 B

    int tid  = threadIdx.x;
    int m0   = blockIdx.x * GM;
    int warp = tid >> 5;
    int lane = tid & 31;
    int gid  = lane >> 2;      // 0..7
    int tig  = lane & 3;       // 0..3
    int mw   = warp * 16;

    float acc[8][4];
#pragma unroll
    for (int j = 0; j < 8; j++)
#pragma unroll
        for (int q = 0; q < 4; q++) acc[j][q] = 0.0f;

    for (int k0 = 0; k0 < IN_SIZE; k0 += GK) {
        // stage A tile: 128 rows x 32 k, coalesced float4 loads
#pragma unroll
        for (int it = 0; it < 4; it++) {
            int idx = tid + it * 256;      // 0..1023
            int m   = idx >> 3;            // 0..127
            int kq  = idx & 7;             // 0..7
            float4 v = make_float4(0.f, 0.f, 0.f, 0.f);
            if (m0 + m < N)
                v = *reinterpret_cast<const float4*>(&x[(size_t)(m0 + m) * IN_SIZE + k0 + kq * 4]);
            uint32_t* p = &s_a[m * AS_STRIDE + kq * 4];
            p[0] = f2tf(v.x); p[1] = f2tf(v.y); p[2] = f2tf(v.z); p[3] = f2tf(v.w);
        }
        // stage W^T tile: 32 k x 64 n (already tf32 in g_wt)
#pragma unroll
        for (int it = 0; it < 2; it++) {
            int idx = tid + it * 256;      // 0..511
            int k   = idx >> 4;            // 0..31
            int nq  = idx & 15;            // 0..15
            uint4 v = *reinterpret_cast<const uint4*>(&g_wt[(k0 + k) * OUT_SIZE + nq * 4]);
            *reinterpret_cast<uint4*>(&s_w[k * WS_STRIDE + nq * 4]) = v;
        }
        __syncthreads();

#pragma unroll
        for (int ks = 0; ks < 4; ks++) {
            int kk = ks * 8;
            uint32_t a0 = s_a[(mw + gid)     * AS_STRIDE + kk + tig];
            uint32_t a1 = s_a[(mw + gid + 8) * AS_STRIDE + kk + tig];
            uint32_t a2 = s_a[(mw + gid)     * AS_STRIDE + kk + tig + 4];
            uint32_t a3 = s_a[(mw + gid + 8) * AS_STRIDE + kk + tig + 4];
#pragma unroll
            for (int j = 0; j < 8; j++) {
                uint32_t b0 = s_w[(kk + tig)     * WS_STRIDE + j * 8 + gid];
                uint32_t b1 = s_w[(kk + tig + 4) * WS_STRIDE + j * 8 + gid];
                asm volatile(
                    "mma.sync.aligned.m16n8k8.row.col.f32.tf32.tf32.f32 "
                    "{%0,%1,%2,%3}, {%4,%5,%6,%7}, {%8,%9}, {%0,%1,%2,%3};"
                    : "+f"(acc[j][0]), "+f"(acc[j][1]), "+f"(acc[j][2]), "+f"(acc[j][3])
                    : "r"(a0), "r"(a1), "r"(a2), "r"(a3), "r"(b0), "r"(b1));
            }
        }
        __syncthreads();
    }

    // epilogue: d0=(g,2t) d1=(g,2t+1) d2=(g+8,2t) d3=(g+8,2t+1)
    int r0 = m0 + mw + gid;
#pragma unroll
    for (int j = 0; j < 8; j++) {
        if (r0 < N)
            *reinterpret_cast<float2*>(&g_xw[(size_t)r0 * OUT_SIZE + j * 8 + 2 * tig]) =
                make_float2(acc[j][0], acc[j][1]);
        if (r0 + 8 < N)
            *reinterpret_cast<float2*>(&g_xw[(size_t)(r0 + 8) * OUT_SIZE + j * 8 + 2 * tig]) =
                make_float2(acc[j][2], acc[j][3]);
    }
}

// ---------------- CSR aggregation (self-loop fused, no atomics) ----------------
// out[r,:] = dinv[r] * ( dinv[r]*xw[r,:] + sum_c dinv[c]*xw[c,:] )
__global__ __launch_bounds__(256) void k_agg(float* __restrict__ out, int N) {
    int t   = blockIdx.x * blockDim.x + threadIdx.x;
    int row = t >> 4;
    int l   = t & 15;
    if (row >= N) return;

    const float4* xw4 = reinterpret_cast<const float4*>(g_xw);
    float dr = g_dinv[row];

    float4 a = xw4[(size_t)row * 16 + l];
    float4 acc;
    acc.x = dr * a.x; acc.y = dr * a.y; acc.z = dr * a.z; acc.w = dr * a.w;

    int s0  = g_rowstart[row];
    int cnt = g_deg[row];
#pragma unroll 4
    for (int j = 0; j < cnt; j++) {
        int   c  = g_col[s0 + j];
        float sc = g_dinv[c];
        float4 v = xw4[(size_t)c * 16 + l];
        acc.x = fmaf(sc, v.x, acc.x);
        acc.y = fmaf(sc, v.y, acc.y);
        acc.z = fmaf(sc, v.z, acc.z);
        acc.w = fmaf(sc, v.w, acc.w);
    }

    float4 o;
    o.x = dr * acc.x; o.y = dr * acc.y; o.z = dr * acc.z; o.w = dr * acc.w;
    reinterpret_cast<float4*>(out)[(size_t)row * 16 + l] = o;
}

// ---------------------------------------------------------------------------
extern "C" void kernel_launch(void* const* d_in, const int* in_sizes, int n_in,
                              void* d_out, int out_size) {
    const int*   ei = (const int*)d_in[0];     // [2, E]
    const float* x  = (const float*)d_in[1];   // [N, 256]
    const float* W  = (const float*)d_in[3];   // [64, 256]
    float* out = (float*)d_out;

    int E  = in_sizes[0] / 2;
    int N  = in_sizes[1] / IN_SIZE;
    int NB = (N + 1023) >> 10;

    k_zero_deg<<<(N + 255) / 256, 256>>>(N);
    k_count  <<<(E + 255) / 256, 256>>>(ei, E);
    k_dinv   <<<(N + 255) / 256, 256>>>(N);
    k_scan1  <<<NB, 1024>>>(N);
    k_scan2  <<<1, 128>>>(NB);
    k_scan3  <<<(N + 255) / 256, 256>>>(N);
    k_scatter<<<(E + 255) / 256, 256>>>(ei, E);
    k_wt     <<<(IN_SIZE * OUT_SIZE + 255) / 256, 256>>>(W);
    k_gemm   <<<(N + GM - 1) / GM, 256>>>(x, N);
    k_agg    <<<(N + 15) / 16, 256>>>(out, N);
}

// round 5
// speedup vs baseline: 1.8843x; 1.1695x over previous
#include <cuda_runtime.h>
#include <math.h>
#include <stdint.h>

#define MAXN 100000
#define MAXE 1600000
#define IN_SIZE 256
#define OUT_SIZE 64

// ---------------- device scratch (no allocation allowed) ----------------
__device__ __align__(256) float    g_xw[MAXN * OUT_SIZE];       // X @ W^T
__device__ __align__(256) uint32_t g_wt[IN_SIZE * OUT_SIZE];    // W^T tf32, [k][n]
__device__ __align__(256) float    g_dinv[MAXN];                // D^{-1/2}
__device__ __align__(256) int      g_deg[MAXN];                 // non-self degree
__device__ __align__(256) int      g_rowstart[MAXN];            // per-block-exclusive scan
__device__ __align__(256) int      g_bsum[128];
__device__ __align__(256) int      g_boff[128];
__device__ __align__(256) int      g_slot[MAXE];                // per-edge slot in row
__device__ __align__(256) int      g_col[MAXE];                 // CSR column indices

__device__ __forceinline__ uint32_t f2tf(float f) {
    uint32_t r;
    asm("cvt.rna.tf32.f32 %0, %1;" : "=r"(r) : "f"(f));
    return r;
}

__device__ __forceinline__ void cp16(void* smem, const void* g, int valid) {
    uint32_t s = (uint32_t)__cvta_generic_to_shared(smem);
    asm volatile("cp.async.cg.shared.global [%0], [%1], 16, %2;"
                 :: "r"(s), "l"(g), "r"(valid ? 16 : 0));
}
__device__ __forceinline__ void cp_commit() { asm volatile("cp.async.commit_group;"); }
template <int n> __device__ __forceinline__ void cp_wait() {
    asm volatile("cp.async.wait_group %0;" :: "n"(n));
}

// ---------------- init: zero degrees + W^T tf32 convert ----------------
__global__ void k_init(const float* __restrict__ W, int N) {
    int i = blockIdx.x * blockDim.x + threadIdx.x;
    if (i < N) g_deg[i] = 0;
    if (i < IN_SIZE * OUT_SIZE) {
        int k = i >> 6;
        int n = i & 63;
        g_wt[i] = f2tf(W[n * IN_SIZE + k]);
    }
}

// ---------------- count non-self edges, record slot ----------------
__global__ void k_count(const int* __restrict__ ei, int E) {
    int e = blockIdx.x * blockDim.x + threadIdx.x;
    if (e < E) {
        int r = ei[e];
        int c = ei[E + e];
        if (r != c) g_slot[e] = atomicAdd(&g_deg[r], 1);
    }
}

// ---------------- scan level 1 (shfl-based) + dinv fused ----------------
__global__ __launch_bounds__(1024) void k_scan1(int N) {
    __shared__ int wsum[32];
    int i = blockIdx.x * 1024 + threadIdx.x;
    int v = (i < N) ? g_deg[i] : 0;
    if (i < N) g_dinv[i] = rsqrtf((float)(v + 1));   // +1: self loop

    int lane = threadIdx.x & 31;
    int w    = threadIdx.x >> 5;
    int p = v;                                        // inclusive warp scan
#pragma unroll
    for (int off = 1; off < 32; off <<= 1) {
        int t = __shfl_up_sync(0xffffffffu, p, off);
        if (lane >= off) p += t;
    }
    if (lane == 31) wsum[w] = p;
    __syncthreads();
    if (w == 0) {
        int s = wsum[lane];
#pragma unroll
        for (int off = 1; off < 32; off <<= 1) {
            int t = __shfl_up_sync(0xffffffffu, s, off);
            if (lane >= off) s += t;
        }
        wsum[lane] = s;                               // inclusive over warps
    }
    __syncthreads();
    int base = (w > 0) ? wsum[w - 1] : 0;
    if (i < N) g_rowstart[i] = base + p - v;          // block-exclusive
    if (threadIdx.x == 0) g_bsum[blockIdx.x] = wsum[31];
}

// ---------------- scan level 2 (<=128 blocks) ----------------
__global__ void k_scan2(int NB) {
    __shared__ int s[128];
    int v = (threadIdx.x < NB) ? g_bsum[threadIdx.x] : 0;
    s[threadIdx.x] = v;
    __syncthreads();
    for (int off = 1; off < 128; off <<= 1) {
        int t = (threadIdx.x >= off) ? s[threadIdx.x - off] : 0;
        __syncthreads();
        s[threadIdx.x] += t;
        __syncthreads();
    }
    if (threadIdx.x < NB) g_boff[threadIdx.x] = s[threadIdx.x] - v;
}

// ---------------- scatter CSR columns (block offset applied inline) ----------------
__global__ void k_scatter(const int* __restrict__ ei, int E) {
    int e = blockIdx.x * blockDim.x + threadIdx.x;
    if (e < E) {
        int r = ei[e];
        int c = ei[E + e];
        if (r != c) {
            int rs = g_rowstart[r] + g_boff[r >> 10];
            g_col[rs + g_slot[e]] = c;
        }
    }
}

// ---------------- GEMM: g_xw[N,64] = x[N,256] @ W^T, tf32 mma, cp.async ----------------
#define GM 128
#define GK 32
#define AS 36     // floats per A row (9 x 16B)
#define WS 72     // u32 per W k-row (18 x 16B)
#define A_BUF (GM * AS)       // 4608 floats
#define W_BUF (GK * WS)       // 2304 u32
#define GEMM_SMEM ((2 * A_BUF + 2 * W_BUF) * 4)   // 55296 B

__global__ __launch_bounds__(256) void k_gemm(const float* __restrict__ x, int N) {
    extern __shared__ float dyn[];
    float*    sA0 = dyn;
    float*    sA1 = dyn + A_BUF;
    uint32_t* sW0 = reinterpret_cast<uint32_t*>(dyn + 2 * A_BUF);
    uint32_t* sW1 = sW0 + W_BUF;
    float*    sA[2] = {sA0, sA1};
    uint32_t* sW[2] = {sW0, sW1};

    int tid  = threadIdx.x;
    int m0   = blockIdx.x * GM;
    int warp = tid >> 5;
    int lane = tid & 31;
    int gid  = lane >> 2;      // 0..7
    int tig  = lane & 3;       // 0..3
    int mw   = warp * 16;

    float acc[8][4];
#pragma unroll
    for (int j = 0; j < 8; j++)
#pragma unroll
        for (int q = 0; q < 4; q++) acc[j][q] = 0.0f;

    auto loadA = [&](int k0, float* buf) {
#pragma unroll
        for (int it = 0; it < 4; it++) {
            int idx = tid + it * 256;      // 0..1023
            int m   = idx >> 3;            // 0..127
            int kq  = idx & 7;             // 0..7
            int gm  = m0 + m;
            int ok  = gm < N;
            int row = ok ? gm : 0;
            cp16(&buf[m * AS + kq * 4],
                 &x[(size_t)row * IN_SIZE + k0 + kq * 4], ok);
        }
    };
    auto loadW = [&](int k0, uint32_t* buf) {
#pragma unroll
        for (int it = 0; it < 2; it++) {
            int idx = tid + it * 256;      // 0..511
            int k   = idx >> 4;            // 0..31
            int nq  = idx & 15;            // 0..15
            cp16(&buf[k * WS + nq * 4], &g_wt[(k0 + k) * OUT_SIZE + nq * 4], 1);
        }
    };

    loadA(0, sA[0]);
    loadW(0, sW[0]);
    cp_commit();

#pragma unroll 1
    for (int i = 0; i < IN_SIZE / GK; i++) {
        if (i < IN_SIZE / GK - 1) {
            loadA((i + 1) * GK, sA[(i + 1) & 1]);
            loadW((i + 1) * GK, sW[(i + 1) & 1]);
            cp_commit();
            cp_wait<1>();
        } else {
            cp_wait<0>();
        }
        __syncthreads();

        const float*    a_s = sA[i & 1];
        const uint32_t* w_s = sW[i & 1];
#pragma unroll
        for (int ks = 0; ks < 4; ks++) {
            int kk = ks * 8;
            uint32_t a0 = f2tf(a_s[(mw + gid)     * AS + kk + tig]);
            uint32_t a1 = f2tf(a_s[(mw + gid + 8) * AS + kk + tig]);
            uint32_t a2 = f2tf(a_s[(mw + gid)     * AS + kk + tig + 4]);
            uint32_t a3 = f2tf(a_s[(mw + gid + 8) * AS + kk + tig + 4]);
#pragma unroll
            for (int j = 0; j < 8; j++) {
                uint32_t b0 = w_s[(kk + tig)     * WS + j * 8 + gid];
                uint32_t b1 = w_s[(kk + tig + 4) * WS + j * 8 + gid];
                asm volatile(
                    "mma.sync.aligned.m16n8k8.row.col.f32.tf32.tf32.f32 "
                    "{%0,%1,%2,%3}, {%4,%5,%6,%7}, {%8,%9}, {%0,%1,%2,%3};"
                    : "+f"(acc[j][0]), "+f"(acc[j][1]), "+f"(acc[j][2]), "+f"(acc[j][3])
                    : "r"(a0), "r"(a1), "r"(a2), "r"(a3), "r"(b0), "r"(b1));
            }
        }
        __syncthreads();
    }

    int r0 = m0 + mw + gid;
#pragma unroll
    for (int j = 0; j < 8; j++) {
        if (r0 < N)
            *reinterpret_cast<float2*>(&g_xw[(size_t)r0 * OUT_SIZE + j * 8 + 2 * tig]) =
                make_float2(acc[j][0], acc[j][1]);
        if (r0 + 8 < N)
            *reinterpret_cast<float2*>(&g_xw[(size_t)(r0 + 8) * OUT_SIZE + j * 8 + 2 * tig]) =
                make_float2(acc[j][2], acc[j][3]);
    }
}

// ---------------- CSR aggregation (self-loop fused, no atomics) ----------------
__global__ __launch_bounds__(256) void k_agg(float* __restrict__ out, int N) {
    int t   = blockIdx.x * blockDim.x + threadIdx.x;
    int row = t >> 4;
    int l   = t & 15;
    if (row >= N) return;

    const float4* xw4 = reinterpret_cast<const float4*>(g_xw);
    float dr = g_dinv[row];

    float4 a = xw4[(size_t)row * 16 + l];
    float4 acc;
    acc.x = dr * a.x; acc.y = dr * a.y; acc.z = dr * a.z; acc.w = dr * a.w;

    int s0  = g_rowstart[row] + g_boff[row >> 10];
    int cnt = g_deg[row];

    int j = 0;
    for (; j + 4 <= cnt; j += 4) {
        int c0 = __ldg(&g_col[s0 + j]);
        int c1 = __ldg(&g_col[s0 + j + 1]);
        int c2 = __ldg(&g_col[s0 + j + 2]);
        int c3 = __ldg(&g_col[s0 + j + 3]);
        float sc0 = __ldg(&g_dinv[c0]);
        float sc1 = __ldg(&g_dinv[c1]);
        float sc2 = __ldg(&g_dinv[c2]);
        float sc3 = __ldg(&g_dinv[c3]);
        float4 v0 = xw4[(size_t)c0 * 16 + l];
        float4 v1 = xw4[(size_t)c1 * 16 + l];
        float4 v2 = xw4[(size_t)c2 * 16 + l];
        float4 v3 = xw4[(size_t)c3 * 16 + l];
        acc.x = fmaf(sc0, v0.x, acc.x); acc.y = fmaf(sc0, v0.y, acc.y);
        acc.z = fmaf(sc0, v0.z, acc.z); acc.w = fmaf(sc0, v0.w, acc.w);
        acc.x = fmaf(sc1, v1.x, acc.x); acc.y = fmaf(sc1, v1.y, acc.y);
        acc.z = fmaf(sc1, v1.z, acc.z); acc.w = fmaf(sc1, v1.w, acc.w);
        acc.x = fmaf(sc2, v2.x, acc.x); acc.y = fmaf(sc2, v2.y, acc.y);
        acc.z = fmaf(sc2, v2.z, acc.z); acc.w = fmaf(sc2, v2.w, acc.w);
        acc.x = fmaf(sc3, v3.x, acc.x); acc.y = fmaf(sc3, v3.y, acc.y);
        acc.z = fmaf(sc3, v3.z, acc.z); acc.w = fmaf(sc3, v3.w, acc.w);
    }
    for (; j < cnt; j++) {
        int   c  = __ldg(&g_col[s0 + j]);
        float sc = __ldg(&g_dinv[c]);
        float4 v = xw4[(size_t)c * 16 + l];
        acc.x = fmaf(sc, v.x, acc.x); acc.y = fmaf(sc, v.y, acc.y);
        acc.z = fmaf(sc, v.z, acc.z); acc.w = fmaf(sc, v.w, acc.w);
    }

    float4 o;
    o.x = dr * acc.x; o.y = dr * acc.y; o.z = dr * acc.z; o.w = dr * acc.w;
    reinterpret_cast<float4*>(out)[(size_t)row * 16 + l] = o;
}

// ---------------------------------------------------------------------------
extern "C" void kernel_launch(void* const* d_in, const int* in_sizes, int n_in,
                              void* d_out, int out_size) {
    const int*   ei = (const int*)d_in[0];     // [2, E]
    const float* x  = (const float*)d_in[1];   // [N, 256]
    const float* W  = (const float*)d_in[3];   // [64, 256]
    float* out = (float*)d_out;

    int E  = in_sizes[0] / 2;
    int N  = in_sizes[1] / IN_SIZE;
    int NB = (N + 1023) >> 10;

    cudaFuncSetAttribute(k_gemm, cudaFuncAttributeMaxDynamicSharedMemorySize, GEMM_SMEM);

    k_init   <<<(N + 255) / 256, 256>>>(W, N);
    k_count  <<<(E + 255) / 256, 256>>>(ei, E);
    k_scan1  <<<NB, 1024>>>(N);
    k_scan2  <<<1, 128>>>(NB);
    k_scatter<<<(E + 255) / 256, 256>>>(ei, E);
    k_gemm   <<<(N + GM - 1) / GM, 256, GEMM_SMEM>>>(x, N);
    k_agg    <<<(N + 15) / 16, 256>>>(out, N);
}

// round 6
// speedup vs baseline: 2.0809x; 1.1043x over previous
#include <cuda_runtime.h>
#include <cuda_fp16.h>
#include <math.h>
#include <stdint.h>

#define MAXN 100000
#define MAXE 1600000
#define IN_SIZE 256
#define OUT_SIZE 64

// ---------------- device scratch (no allocation allowed) ----------------
__device__ __align__(256) __half    g_xwh[MAXN * OUT_SIZE];     // X @ W^T in fp16
__device__ __align__(256) uint32_t  g_wt[IN_SIZE * OUT_SIZE];   // W^T tf32, [k][n]
__device__ __align__(256) float     g_dinv[MAXN];               // D^{-1/2}
__device__ __align__(256) int       g_deg[MAXN];                // non-self degree
__device__ __align__(256) int       g_rowstart[MAXN];           // global CSR offsets
__device__ __align__(256) int       g_slot[MAXE];               // per-edge slot in row
__device__ __align__(256) int       g_col[MAXE];                // CSR column indices
__device__ int g_total;

__device__ __forceinline__ uint32_t f2tf(float f) {
    uint32_t r;
    asm("cvt.rna.tf32.f32 %0, %1;" : "=r"(r) : "f"(f));
    return r;
}

__device__ __forceinline__ void cp16(void* smem, const void* g, int valid) {
    uint32_t s = (uint32_t)__cvta_generic_to_shared(smem);
    asm volatile("cp.async.cg.shared.global [%0], [%1], 16, %2;"
                 :: "r"(s), "l"(g), "r"(valid ? 16 : 0));
}
__device__ __forceinline__ void cp_commit() { asm volatile("cp.async.commit_group;"); }
template <int n> __device__ __forceinline__ void cp_wait() {
    asm volatile("cp.async.wait_group %0;" :: "n"(n));
}

// ---------------- init: zero degrees/counter + W^T tf32 convert ----------------
__global__ void k_init(const float* __restrict__ W, int N) {
    int i = blockIdx.x * blockDim.x + threadIdx.x;
    if (i == 0) g_total = 0;
    if (i < N) g_deg[i] = 0;
    if (i < IN_SIZE * OUT_SIZE) {
        int k = i >> 6;
        int n = i & 63;
        g_wt[i] = f2tf(W[n * IN_SIZE + k]);
    }
}

// ---------------- count non-self edges, record slot ----------------
__global__ void k_count(const int* __restrict__ ei, int E) {
    int e = blockIdx.x * blockDim.x + threadIdx.x;
    if (e < E) {
        int r = ei[e];
        int c = ei[E + e];
        if (r != c) g_slot[e] = atomicAdd(&g_deg[r], 1);
    }
}

// ---------------- offsets: block shfl-scan + atomic block base; dinv fused ----------------
__global__ __launch_bounds__(1024) void k_offsets(int N) {
    __shared__ int wsum[32];
    __shared__ int sbase;
    int i = blockIdx.x * 1024 + threadIdx.x;
    int v = (i < N) ? g_deg[i] : 0;
    if (i < N) g_dinv[i] = rsqrtf((float)(v + 1));   // +1: self loop

    int lane = threadIdx.x & 31;
    int w    = threadIdx.x >> 5;
    int p = v;                                        // inclusive warp scan
#pragma unroll
    for (int off = 1; off < 32; off <<= 1) {
        int t = __shfl_up_sync(0xffffffffu, p, off);
        if (lane >= off) p += t;
    }
    if (lane == 31) wsum[w] = p;
    __syncthreads();
    if (w == 0) {
        int s = wsum[lane];
#pragma unroll
        for (int off = 1; off < 32; off <<= 1) {
            int t = __shfl_up_sync(0xffffffffu, s, off);
            if (lane >= off) s += t;
        }
        wsum[lane] = s;                               // inclusive over warps
        if (lane == 31) sbase = atomicAdd(&g_total, s);
    }
    __syncthreads();
    int base = (w > 0) ? wsum[w - 1] : 0;
    if (i < N) g_rowstart[i] = sbase + base + p - v;  // global exclusive offset
}

// ---------------- scatter CSR columns ----------------
__global__ void k_scatter(const int* __restrict__ ei, int E) {
    int e = blockIdx.x * blockDim.x + threadIdx.x;
    if (e < E) {
        int r = ei[e];
        int c = ei[E + e];
        if (r != c) g_col[g_rowstart[r] + g_slot[e]] = c;
    }
}

// ---------------- GEMM: g_xwh[N,64] = x[N,256] @ W^T, tf32 mma, cp.async ----------------
#define GM 128
#define GK 32
#define AS 36     // floats per A row (9 x 16B)
#define WS 72     // u32 per W k-row (18 x 16B)
#define A_BUF (GM * AS)
#define W_BUF (GK * WS)
#define GEMM_SMEM ((2 * A_BUF + 2 * W_BUF) * 4)   // 55296 B

__global__ __launch_bounds__(256) void k_gemm(const float* __restrict__ x, int N) {
    extern __shared__ float dyn[];
    float*    sA[2] = {dyn, dyn + A_BUF};
    uint32_t* sWb   = reinterpret_cast<uint32_t*>(dyn + 2 * A_BUF);
    uint32_t* sW[2] = {sWb, sWb + W_BUF};

    int tid  = threadIdx.x;
    int m0   = blockIdx.x * GM;
    int warp = tid >> 5;
    int lane = tid & 31;
    int gid  = lane >> 2;      // 0..7
    int tig  = lane & 3;       // 0..3
    int mw   = warp * 16;

    float acc[8][4];
#pragma unroll
    for (int j = 0; j < 8; j++)
#pragma unroll
        for (int q = 0; q < 4; q++) acc[j][q] = 0.0f;

    auto loadA = [&](int k0, float* buf) {
#pragma unroll
        for (int it = 0; it < 4; it++) {
            int idx = tid + it * 256;
            int m   = idx >> 3;
            int kq  = idx & 7;
            int gm  = m0 + m;
            int ok  = gm < N;
            int row = ok ? gm : 0;
            cp16(&buf[m * AS + kq * 4], &x[(size_t)row * IN_SIZE + k0 + kq * 4], ok);
        }
    };
    auto loadW = [&](int k0, uint32_t* buf) {
#pragma unroll
        for (int it = 0; it < 2; it++) {
            int idx = tid + it * 256;
            int k   = idx >> 4;
            int nq  = idx & 15;
            cp16(&buf[k * WS + nq * 4], &g_wt[(k0 + k) * OUT_SIZE + nq * 4], 1);
        }
    };

    loadA(0, sA[0]);
    loadW(0, sW[0]);
    cp_commit();

#pragma unroll 1
    for (int i = 0; i < IN_SIZE / GK; i++) {
        if (i < IN_SIZE / GK - 1) {
            loadA((i + 1) * GK, sA[(i + 1) & 1]);
            loadW((i + 1) * GK, sW[(i + 1) & 1]);
            cp_commit();
            cp_wait<1>();
        } else {
            cp_wait<0>();
        }
        __syncthreads();

        const float*    a_s = sA[i & 1];
        const uint32_t* w_s = sW[i & 1];
#pragma unroll
        for (int ks = 0; ks < 4; ks++) {
            int kk = ks * 8;
            uint32_t a0 = f2tf(a_s[(mw + gid)     * AS + kk + tig]);
            uint32_t a1 = f2tf(a_s[(mw + gid + 8) * AS + kk + tig]);
            uint32_t a2 = f2tf(a_s[(mw + gid)     * AS + kk + tig + 4]);
            uint32_t a3 = f2tf(a_s[(mw + gid + 8) * AS + kk + tig + 4]);
#pragma unroll
            for (int j = 0; j < 8; j++) {
                uint32_t b0 = w_s[(kk + tig)     * WS + j * 8 + gid];
                uint32_t b1 = w_s[(kk + tig + 4) * WS + j * 8 + gid];
                asm volatile(
                    "mma.sync.aligned.m16n8k8.row.col.f32.tf32.tf32.f32 "
                    "{%0,%1,%2,%3}, {%4,%5,%6,%7}, {%8,%9}, {%0,%1,%2,%3};"
                    : "+f"(acc[j][0]), "+f"(acc[j][1]), "+f"(acc[j][2]), "+f"(acc[j][3])
                    : "r"(a0), "r"(a1), "r"(a2), "r"(a3), "r"(b0), "r"(b1));
            }
        }
        __syncthreads();
    }

    // epilogue -> fp16: d0=(g,2t) d1=(g,2t+1) d2=(g+8,2t) d3=(g+8,2t+1)
    int r0 = m0 + mw + gid;
#pragma unroll
    for (int j = 0; j < 8; j++) {
        if (r0 < N) {
            __half2 h = __floats2half2_rn(acc[j][0], acc[j][1]);
            *reinterpret_cast<__half2*>(&g_xwh[(size_t)r0 * OUT_SIZE + j * 8 + 2 * tig]) = h;
        }
        if (r0 + 8 < N) {
            __half2 h = __floats2half2_rn(acc[j][2], acc[j][3]);
            *reinterpret_cast<__half2*>(&g_xwh[(size_t)(r0 + 8) * OUT_SIZE + j * 8 + 2 * tig]) = h;
        }
    }
}

// ---------------- CSR aggregation (fp16 gather, fp32 accumulate, no atomics) ------
__device__ __forceinline__ void h8_fma(uint4 v, float s, float* acc) {
    const __half2* h = reinterpret_cast<const __half2*>(&v);
#pragma unroll
    for (int q = 0; q < 4; q++) {
        float2 f = __half22float2(h[q]);
        acc[2 * q]     = fmaf(s, f.x, acc[2 * q]);
        acc[2 * q + 1] = fmaf(s, f.y, acc[2 * q + 1]);
    }
}

__global__ __launch_bounds__(256) void k_agg(float* __restrict__ out, int N) {
    int t   = blockIdx.x * blockDim.x + threadIdx.x;
    int row = t >> 3;          // 8 lanes per row
    int l   = t & 7;
    if (row >= N) return;

    const uint4* xh = reinterpret_cast<const uint4*>(g_xwh);   // 8 uint4 per row
    float dr = g_dinv[row];

    float acc[8];
#pragma unroll
    for (int q = 0; q < 8; q++) acc[q] = 0.0f;
    h8_fma(xh[(size_t)row * 8 + l], dr, acc);                  // self loop (dinv[r]*xw[r])

    int s0  = g_rowstart[row];
    int cnt = g_deg[row];

    int j = 0;
    for (; j + 4 <= cnt; j += 4) {
        int c0 = __ldg(&g_col[s0 + j]);
        int c1 = __ldg(&g_col[s0 + j + 1]);
        int c2 = __ldg(&g_col[s0 + j + 2]);
        int c3 = __ldg(&g_col[s0 + j + 3]);
        float sc0 = __ldg(&g_dinv[c0]);
        float sc1 = __ldg(&g_dinv[c1]);
        float sc2 = __ldg(&g_dinv[c2]);
        float sc3 = __ldg(&g_dinv[c3]);
        uint4 v0 = xh[(size_t)c0 * 8 + l];
        uint4 v1 = xh[(size_t)c1 * 8 + l];
        uint4 v2 = xh[(size_t)c2 * 8 + l];
        uint4 v3 = xh[(size_t)c3 * 8 + l];
        h8_fma(v0, sc0, acc);
        h8_fma(v1, sc1, acc);
        h8_fma(v2, sc2, acc);
        h8_fma(v3, sc3, acc);
    }
    for (; j < cnt; j++) {
        int   c  = __ldg(&g_col[s0 + j]);
        float sc = __ldg(&g_dinv[c]);
        h8_fma(xh[(size_t)c * 8 + l], sc, acc);
    }

    float4 o0 = make_float4(dr * acc[0], dr * acc[1], dr * acc[2], dr * acc[3]);
    float4 o1 = make_float4(dr * acc[4], dr * acc[5], dr * acc[6], dr * acc[7]);
    float4* dst = reinterpret_cast<float4*>(out + (size_t)row * OUT_SIZE + l * 8);
    dst[0] = o0;
    dst[1] = o1;
}

// ---------------------------------------------------------------------------
extern "C" void kernel_launch(void* const* d_in, const int* in_sizes, int n_in,
                              void* d_out, int out_size) {
    const int*   ei = (const int*)d_in[0];     // [2, E]
    const float* x  = (const float*)d_in[1];   // [N, 256]
    const float* W  = (const float*)d_in[3];   // [64, 256]
    float* out = (float*)d_out;

    int E  = in_sizes[0] / 2;
    int N  = in_sizes[1] / IN_SIZE;
    int NB = (N + 1023) >> 10;

    cudaFuncSetAttribute(k_gemm, cudaFuncAttributeMaxDynamicSharedMemorySize, GEMM_SMEM);

    k_init   <<<(N + 255) / 256, 256>>>(W, N);
    k_count  <<<(E + 255) / 256, 256>>>(ei, E);
    k_offsets<<<NB, 1024>>>(N);
    k_scatter<<<(E + 255) / 256, 256>>>(ei, E);
    k_gemm   <<<(N + GM - 1) / GM, 256, GEMM_SMEM>>>(x, N);
    k_agg    <<<(N * 8 + 255) / 256, 256>>>(out, N);
}

// round 9
// speedup vs baseline: 2.1198x; 1.0187x over previous
#include <cuda_runtime.h>
#include <cuda_fp16.h>
#include <math.h>
#include <stdint.h>

#define MAXN 100000
#define MAXE 1600000
#define IN_SIZE 256
#define OUT_SIZE 64

// ---------------- device scratch (no allocation allowed) ----------------
__device__ __align__(256) __half    g_xwh[MAXN * OUT_SIZE];     // X @ W^T in fp16
__device__ __align__(256) uint32_t  g_wt[IN_SIZE * OUT_SIZE];   // W^T tf32, [k][n]
__device__ __align__(256) float     g_dinv[MAXN];               // D^{-1/2}
__device__ __align__(256) int       g_deg[MAXN];                // non-self degree
__device__ __align__(256) int       g_rowstart[MAXN];           // global CSR offsets
__device__ __align__(256) int       g_slot[MAXE];               // per-edge slot in row
__device__ __align__(256) int       g_col[MAXE];                // CSR column indices
__device__ int      g_total;
__device__ unsigned g_barctr;

__device__ __forceinline__ uint32_t f2tf(float f) {
    uint32_t r;
    asm("cvt.rna.tf32.f32 %0, %1;" : "=r"(r) : "f"(f));
    return r;
}

__device__ __forceinline__ void cp16(void* smem, const void* g, int valid) {
    uint32_t s = (uint32_t)__cvta_generic_to_shared(smem);
    asm volatile("cp.async.cg.shared.global [%0], [%1], 16, %2;"
                 :: "r"(s), "l"(g), "r"(valid ? 16 : 0));
}
__device__ __forceinline__ void cp_commit() { asm volatile("cp.async.commit_group;"); }
template <int n> __device__ __forceinline__ void cp_wait() {
    asm volatile("cp.async.wait_group %0;" :: "n"(n));
}

// CSR-group barrier: release arrive on L2 counter, acquire spin, block fan-in/out.
__device__ __forceinline__ void csr_barrier(unsigned target) {
    __syncthreads();
    if (threadIdx.x == 0) {
        __threadfence();
        atomicAdd(&g_barctr, 1u);
        unsigned v;
        do {
            asm volatile("ld.acquire.gpu.u32 %0, [%1];" : "=r"(v) : "l"(&g_barctr) : "memory");
            if (v < target) __nanosleep(64);
        } while (v < target);
    }
    __syncthreads();
}

// ---------------- reset: counters, degrees, W^T tf32 ----------------
__global__ void k_reset(const float* __restrict__ W, int N) {
    int i = blockIdx.x * blockDim.x + threadIdx.x;
    if (i == 0) { g_barctr = 0u; g_total = 0; }
    if (i < N) g_deg[i] = 0;
    if (i < IN_SIZE * OUT_SIZE) {
        int k = i >> 6;
        int n = i & 63;
        g_wt[i] = f2tf(W[n * IN_SIZE + k]);
    }
}

// ---------------- mega kernel: GEMM blocks || CSR-build blocks ----------------
#define GM 128
#define GK 32
#define AS 36
#define WS 72
#define A_BUF (GM * AS)
#define W_BUF (GK * WS)
#define GEMM_SMEM ((2 * A_BUF + 2 * W_BUF) * 4)   // 55296 B

__global__ __launch_bounds__(256) void k_mega(const int* __restrict__ ei,
                                              const float* __restrict__ x,
                                              int N, int E, int tiles,
                                              int gemmBlocks, int nCsr) {
    extern __shared__ float dyn[];
    int tid = threadIdx.x;

    if ((int)blockIdx.x < gemmBlocks) {
        // ================= GEMM role: persistent tiles =================
        float*    sA[2] = {dyn, dyn + A_BUF};
        uint32_t* sWb   = reinterpret_cast<uint32_t*>(dyn + 2 * A_BUF);
        uint32_t* sW[2] = {sWb, sWb + W_BUF};

        int warp = tid >> 5;
        int lane = tid & 31;
        int gid  = lane >> 2;
        int tig  = lane & 3;
        int mw   = warp * 16;

        auto loadA = [&](int m0, int k0, float* buf) {
#pragma unroll
            for (int it = 0; it < 4; it++) {
                int idx = tid + it * 256;
                int m   = idx >> 3;
                int kq  = idx & 7;
                int gm  = m0 + m;
                int ok  = gm < N;
                int row = ok ? gm : 0;
                cp16(&buf[m * AS + kq * 4], &x[(size_t)row * IN_SIZE + k0 + kq * 4], ok);
            }
        };
        auto loadW = [&](int k0, uint32_t* buf) {
#pragma unroll
            for (int it = 0; it < 2; it++) {
                int idx = tid + it * 256;
                int k   = idx >> 4;
                int nq  = idx & 15;
                cp16(&buf[k * WS + nq * 4], &g_wt[(k0 + k) * OUT_SIZE + nq * 4], 1);
            }
        };

        for (int t = blockIdx.x; t < tiles; t += gemmBlocks) {
            int m0 = t * GM;

            float acc[8][4];
#pragma unroll
            for (int j = 0; j < 8; j++)
#pragma unroll
                for (int q = 0; q < 4; q++) acc[j][q] = 0.0f;

            loadA(m0, 0, sA[0]);
            loadW(0, sW[0]);
            cp_commit();

#pragma unroll 1
            for (int i = 0; i < IN_SIZE / GK; i++) {
                if (i < IN_SIZE / GK - 1) {
                    loadA(m0, (i + 1) * GK, sA[(i + 1) & 1]);
                    loadW((i + 1) * GK, sW[(i + 1) & 1]);
                    cp_commit();
                    cp_wait<1>();
                } else {
                    cp_wait<0>();
                }
                __syncthreads();

                const float*    a_s = sA[i & 1];
                const uint32_t* w_s = sW[i & 1];
#pragma unroll
                for (int ks = 0; ks < 4; ks++) {
                    int kk = ks * 8;
                    uint32_t a0 = f2tf(a_s[(mw + gid)     * AS + kk + tig]);
                    uint32_t a1 = f2tf(a_s[(mw + gid + 8) * AS + kk + tig]);
                    uint32_t a2 = f2tf(a_s[(mw + gid)     * AS + kk + tig + 4]);
                    uint32_t a3 = f2tf(a_s[(mw + gid + 8) * AS + kk + tig + 4]);
#pragma unroll
                    for (int j = 0; j < 8; j++) {
                        uint32_t b0 = w_s[(kk + tig)     * WS + j * 8 + gid];
                        uint32_t b1 = w_s[(kk + tig + 4) * WS + j * 8 + gid];
                        asm volatile(
                            "mma.sync.aligned.m16n8k8.row.col.f32.tf32.tf32.f32 "
                            "{%0,%1,%2,%3}, {%4,%5,%6,%7}, {%8,%9}, {%0,%1,%2,%3};"
                            : "+f"(acc[j][0]), "+f"(acc[j][1]), "+f"(acc[j][2]), "+f"(acc[j][3])
                            : "r"(a0), "r"(a1), "r"(a2), "r"(a3), "r"(b0), "r"(b1));
                    }
                }
                __syncthreads();
            }

            int r0 = m0 + mw + gid;
#pragma unroll
            for (int j = 0; j < 8; j++) {
                if (r0 < N) {
                    __half2 h = __floats2half2_rn(acc[j][0], acc[j][1]);
                    *reinterpret_cast<__half2*>(&g_xwh[(size_t)r0 * OUT_SIZE + j * 8 + 2 * tig]) = h;
                }
                if (r0 + 8 < N) {
                    __half2 h = __floats2half2_rn(acc[j][2], acc[j][3]);
                    *reinterpret_cast<__half2*>(&g_xwh[(size_t)(r0 + 8) * OUT_SIZE + j * 8 + 2 * tig]) = h;
                }
            }
            __syncthreads();   // protect smem before next tile's prologue
        }
    } else {
        // ================= CSR role: count -> scan -> scatter =================
        int csrRank = blockIdx.x - gemmBlocks;
        int Tcsr    = nCsr * 256;
        int gtid    = csrRank * 256 + tid;

        // phase 1: count non-self edges, record slot
        for (int e = gtid; e < E; e += Tcsr) {
            int r = ei[e];
            int c = ei[E + e];
            if (r != c) g_slot[e] = atomicAdd(&g_deg[r], 1);
        }
        csr_barrier((unsigned)nCsr);

        // phase 2: chunked exclusive scan of deg -> rowstart; dinv fused
        {
            int* swsum = reinterpret_cast<int*>(dyn);   // 8 ints
            __shared__ int schunkbase;
            int lane = tid & 31;
            int w    = tid >> 5;
            int nChunks = (N + 255) >> 8;
            for (int chunk = csrRank; chunk < nChunks; chunk += nCsr) {
                int i = chunk * 256 + tid;
                int v = (i < N) ? __ldcg(&g_deg[i]) : 0;
                if (i < N) g_dinv[i] = rsqrtf((float)(v + 1));   // +1: self loop
                int p = v;
#pragma unroll
                for (int off = 1; off < 32; off <<= 1) {
                    int tt = __shfl_up_sync(0xffffffffu, p, off);
                    if (lane >= off) p += tt;
                }
                if (lane == 31) swsum[w] = p;
                __syncthreads();
                if (tid == 0) {
                    int run = 0;
#pragma unroll
                    for (int k = 0; k < 8; k++) { int s = swsum[k]; swsum[k] = run; run += s; }
                    schunkbase = atomicAdd(&g_total, run);
                }
                __syncthreads();
                if (i < N) g_rowstart[i] = schunkbase + swsum[w] + p - v;
                __syncthreads();
            }
        }
        csr_barrier((unsigned)(2 * nCsr));

        // phase 3: scatter columns
        for (int e = gtid; e < E; e += Tcsr) {
            int r = ei[e];
            int c = ei[E + e];
            if (r != c) {
                int rs = __ldcg(&g_rowstart[r]);
                int sl = __ldcg(&g_slot[e]);
                g_col[rs + sl] = c;
            }
        }
    }
}

// ---------------- CSR aggregation (fp16 gather, fp32 accumulate) ----------------
__device__ __forceinline__ void h8_fma(uint4 v, float s, float* acc) {
    const __half2* h = reinterpret_cast<const __half2*>(&v);
#pragma unroll
    for (int q = 0; q < 4; q++) {
        float2 f = __half22float2(h[q]);
        acc[2 * q]     = fmaf(s, f.x, acc[2 * q]);
        acc[2 * q + 1] = fmaf(s, f.y, acc[2 * q + 1]);
    }
}

__global__ __launch_bounds__(256) void k_agg(float* __restrict__ out, int N) {
    int t   = blockIdx.x * blockDim.x + threadIdx.x;
    int row = t >> 3;          // 8 lanes per row
    int l   = t & 7;
    if (row >= N) return;

    const uint4* xh = reinterpret_cast<const uint4*>(g_xwh);
    float dr = g_dinv[row];

    float acc[8];
#pragma unroll
    for (int q = 0; q < 8; q++) acc[q] = 0.0f;
    h8_fma(xh[(size_t)row * 8 + l], dr, acc);   // self loop

    int s0  = g_rowstart[row];
    int cnt = g_deg[row];

    int j = 0;
    for (; j + 4 <= cnt; j += 4) {
        int c0 = __ldg(&g_col[s0 + j]);
        int c1 = __ldg(&g_col[s0 + j + 1]);
        int c2 = __ldg(&g_col[s0 + j + 2]);
        int c3 = __ldg(&g_col[s0 + j + 3]);
        float sc0 = __ldg(&g_dinv[c0]);
        float sc1 = __ldg(&g_dinv[c1]);
        float sc2 = __ldg(&g_dinv[c2]);
        float sc3 = __ldg(&g_dinv[c3]);
        uint4 v0 = xh[(size_t)c0 * 8 + l];
        uint4 v1 = xh[(size_t)c1 * 8 + l];
        uint4 v2 = xh[(size_t)c2 * 8 + l];
        uint4 v3 = xh[(size_t)c3 * 8 + l];
        h8_fma(v0, sc0, acc);
        h8_fma(v1, sc1, acc);
        h8_fma(v2, sc2, acc);
        h8_fma(v3, sc3, acc);
    }
    for (; j < cnt; j++) {
        int   c  = __ldg(&g_col[s0 + j]);
        float sc = __ldg(&g_dinv[c]);
        h8_fma(xh[(size_t)c * 8 + l], sc, acc);
    }

    float4 o0 = make_float4(dr * acc[0], dr * acc[1], dr * acc[2], dr * acc[3]);
    float4 o1 = make_float4(dr * acc[4], dr * acc[5], dr * acc[6], dr * acc[7]);
    float4* dst = reinterpret_cast<float4*>(out + (size_t)row * OUT_SIZE + l * 8);
    dst[0] = o0;
    dst[1] = o1;
}

// ---------------------------------------------------------------------------
extern "C" void kernel_launch(void* const* d_in, const int* in_sizes, int n_in,
                              void* d_out, int out_size) {
    const int*   ei = (const int*)d_in[0];     // [2, E]
    const float* x  = (const float*)d_in[1];   // [N, 256]
    const float* W  = (const float*)d_in[3];   // [64, 256]
    float* out = (float*)d_out;

    int E = in_sizes[0] / 2;
    int N = in_sizes[1] / IN_SIZE;

    cudaFuncSetAttribute(k_mega, cudaFuncAttributeMaxDynamicSharedMemorySize, GEMM_SMEM);

    int dev = 0;
    cudaGetDevice(&dev);
    int sms = 0;
    cudaDeviceGetAttribute(&sms, cudaDevAttrMultiProcessorCount, dev);
    int mb = 0;
    cudaOccupancyMaxActiveBlocksPerMultiprocessor(&mb, k_mega, 256, GEMM_SMEM);
    if (mb < 1) mb = 1;
    if (sms < 1) sms = 148;

    int nBlocks = sms * mb;                       // exactly one resident wave
    int tiles   = (N + GM - 1) / GM;
    int gemmB   = (nBlocks * 3) / 8;              // 3/8 GEMM, 5/8 CSR
    if (gemmB < 1) gemmB = 1;
    if (gemmB > nBlocks - 1) gemmB = nBlocks - 1;
    int nCsr = nBlocks - gemmB;

    int initN = N > IN_SIZE * OUT_SIZE ? N : IN_SIZE * OUT_SIZE;
    k_reset<<<(initN + 255) / 256, 256>>>(W, N);
    k_mega <<<nBlocks, 256, GEMM_SMEM>>>(ei, x, N, E, tiles, gemmB, nCsr);
    k_agg  <<<(N * 8 + 255) / 256, 256>>>(out, N);
}

// round 11
// speedup vs baseline: 2.2016x; 1.0386x over previous
#include <cuda_runtime.h>
#include <cuda_fp16.h>
#include <math.h>
#include <stdint.h>

#define MAXN 100000
#define MAXE 1600000
#define IN_SIZE 256
#define OUT_SIZE 64

// ---------------- device scratch (no allocation allowed) ----------------
__device__ __align__(256) __half    g_xwh[MAXN * OUT_SIZE];     // X@W^T fp16 (later *dinv)
__device__ __align__(256) uint32_t  g_wt[IN_SIZE * OUT_SIZE];   // W^T tf32, [k][n]
__device__ __align__(256) float     g_dinv[MAXN];               // D^{-1/2}
__device__ __align__(256) int       g_deg[MAXN];                // non-self degree
__device__ __align__(256) int       g_rowstart[MAXN];           // global CSR offsets
__device__ __align__(256) int       g_slot[MAXE];               // per-edge slot in row
__device__ __align__(256) int       g_col[MAXE];                // CSR column indices
__device__ int      g_total;      // zero-init at load; reset by k_agg each run
__device__ unsigned g_barctr;     // CSR-group barrier counter
__device__ unsigned g_gctr;       // grid-wide barrier counter
__device__ unsigned g_wt_ready;   // W-tf32 ready flag

__device__ __forceinline__ uint32_t f2tf(float f) {
    uint32_t r;
    asm("cvt.rna.tf32.f32 %0, %1;" : "=r"(r) : "f"(f));
    return r;
}

__device__ __forceinline__ void cp16(void* smem, const void* g, int valid) {
    uint32_t s = (uint32_t)__cvta_generic_to_shared(smem);
    asm volatile("cp.async.cg.shared.global [%0], [%1], 16, %2;"
                 :: "r"(s), "l"(g), "r"(valid ? 16 : 0));
}
__device__ __forceinline__ void cp_commit() { asm volatile("cp.async.commit_group;"); }
template <int n> __device__ __forceinline__ void cp_wait() {
    asm volatile("cp.async.wait_group %0;" :: "n"(n));
}

__device__ __forceinline__ unsigned ld_acq(const unsigned* p) {
    unsigned v;
    asm volatile("ld.acquire.gpu.u32 %0, [%1];" : "=r"(v) : "l"(p) : "memory");
    return v;
}
__device__ __forceinline__ void st_rel(unsigned* p, unsigned v) {
    asm volatile("st.release.gpu.u32 [%0], %1;" :: "l"(p), "r"(v) : "memory");
}

// CSR-group barrier: monotonic counter, release arrive, acquire spin.
__device__ __forceinline__ void csr_barrier(unsigned target) {
    __syncthreads();
    if (threadIdx.x == 0) {
        __threadfence();
        atomicAdd(&g_barctr, 1u);
        while (ld_acq(&g_barctr) < target) __nanosleep(64);
    }
    __syncthreads();
}

// ---------------- mega: GEMM blocks || CSR blocks, then barrier + scale ----------------
#define GM 128
#define GK 32
#define AS 36
#define WS 72
#define A_BUF (GM * AS)
#define W_BUF (GK * WS)
#define GEMM_SMEM ((2 * A_BUF + 2 * W_BUF) * 4)   // 55296 B

__global__ __launch_bounds__(256) void k_mega(const int* __restrict__ ei,
                                              const float* __restrict__ x,
                                              const float* __restrict__ W,
                                              int N, int E, int tiles,
                                              int gemmBlocks, int nCsr, int nBlocks) {
    extern __shared__ float dyn[];
    int tid = threadIdx.x;

    if ((int)blockIdx.x < gemmBlocks) {
        // ================= GEMM role =================
        float*    sA[2] = {dyn, dyn + A_BUF};
        uint32_t* sWb   = reinterpret_cast<uint32_t*>(dyn + 2 * A_BUF);
        uint32_t* sW[2] = {sWb, sWb + W_BUF};

        int warp = tid >> 5;
        int lane = tid & 31;
        int gid  = lane >> 2;
        int tig  = lane & 3;
        int mw   = warp * 16;

        // wait for W tf32 (CSR phase 0)
        if (tid == 0) {
            while (ld_acq(&g_wt_ready) == 0u) __nanosleep(64);
        }
        __syncthreads();

        auto loadA = [&](int m0, int k0, float* buf) {
#pragma unroll
            for (int it = 0; it < 4; it++) {
                int idx = tid + it * 256;
                int m   = idx >> 3;
                int kq  = idx & 7;
                int gm  = m0 + m;
                int ok  = gm < N;
                int row = ok ? gm : 0;
                cp16(&buf[m * AS + kq * 4], &x[(size_t)row * IN_SIZE + k0 + kq * 4], ok);
            }
        };
        auto loadW = [&](int k0, uint32_t* buf) {
#pragma unroll
            for (int it = 0; it < 2; it++) {
                int idx = tid + it * 256;
                int k   = idx >> 4;
                int nq  = idx & 15;
                cp16(&buf[k * WS + nq * 4], &g_wt[(k0 + k) * OUT_SIZE + nq * 4], 1);
            }
        };

        for (int t = blockIdx.x; t < tiles; t += gemmBlocks) {
            int m0 = t * GM;

            float acc[8][4];
#pragma unroll
            for (int j = 0; j < 8; j++)
#pragma unroll
                for (int q = 0; q < 4; q++) acc[j][q] = 0.0f;

            loadA(m0, 0, sA[0]);
            loadW(0, sW[0]);
            cp_commit();

#pragma unroll 1
            for (int i = 0; i < IN_SIZE / GK; i++) {
                if (i < IN_SIZE / GK - 1) {
                    loadA(m0, (i + 1) * GK, sA[(i + 1) & 1]);
                    loadW((i + 1) * GK, sW[(i + 1) & 1]);
                    cp_commit();
                    cp_wait<1>();
                } else {
                    cp_wait<0>();
                }
                __syncthreads();

                const float*    a_s = sA[i & 1];
                const uint32_t* w_s = sW[i & 1];
#pragma unroll
                for (int ks = 0; ks < 4; ks++) {
                    int kk = ks * 8;
                    uint32_t a0 = f2tf(a_s[(mw + gid)     * AS + kk + tig]);
                    uint32_t a1 = f2tf(a_s[(mw + gid + 8) * AS + kk + tig]);
                    uint32_t a2 = f2tf(a_s[(mw + gid)     * AS + kk + tig + 4]);
                    uint32_t a3 = f2tf(a_s[(mw + gid + 8) * AS + kk + tig + 4]);
#pragma unroll
                    for (int j = 0; j < 8; j++) {
                        uint32_t b0 = w_s[(kk + tig)     * WS + j * 8 + gid];
                        uint32_t b1 = w_s[(kk + tig + 4) * WS + j * 8 + gid];
                        asm volatile(
                            "mma.sync.aligned.m16n8k8.row.col.f32.tf32.tf32.f32 "
                            "{%0,%1,%2,%3}, {%4,%5,%6,%7}, {%8,%9}, {%0,%1,%2,%3};"
                            : "+f"(acc[j][0]), "+f"(acc[j][1]), "+f"(acc[j][2]), "+f"(acc[j][3])
                            : "r"(a0), "r"(a1), "r"(a2), "r"(a3), "r"(b0), "r"(b1));
                    }
                }
                __syncthreads();
            }

            int r0 = m0 + mw + gid;
#pragma unroll
            for (int j = 0; j < 8; j++) {
                if (r0 < N) {
                    __half2 h = __floats2half2_rn(acc[j][0], acc[j][1]);
                    *reinterpret_cast<__half2*>(&g_xwh[(size_t)r0 * OUT_SIZE + j * 8 + 2 * tig]) = h;
                }
                if (r0 + 8 < N) {
                    __half2 h = __floats2half2_rn(acc[j][2], acc[j][3]);
                    *reinterpret_cast<__half2*>(&g_xwh[(size_t)(r0 + 8) * OUT_SIZE + j * 8 + 2 * tig]) = h;
                }
            }
            __syncthreads();
        }
    } else {
        // ================= CSR role =================
        int csrRank = blockIdx.x - gemmBlocks;
        int Tcsr    = nCsr * 256;
        int gtid    = csrRank * 256 + tid;

        // phase 0: zero degrees + W^T tf32 convert
        for (int i = gtid; i < N; i += Tcsr) g_deg[i] = 0;
        for (int i = gtid; i < IN_SIZE * OUT_SIZE; i += Tcsr) {
            int k = i >> 6;
            int n = i & 63;
            g_wt[i] = f2tf(W[n * IN_SIZE + k]);
        }
        csr_barrier((unsigned)nCsr);
        if (csrRank == 0 && tid == 0) st_rel(&g_wt_ready, 1u);

        // phase 1: count non-self edges, record slot
        for (int e = gtid; e < E; e += Tcsr) {
            int r = ei[e];
            int c = ei[E + e];
            if (r != c) g_slot[e] = atomicAdd(&g_deg[r], 1);
        }
        csr_barrier((unsigned)(2 * nCsr));

        // phase 2: chunked exclusive scan -> rowstart; dinv fused
        {
            int* swsum = reinterpret_cast<int*>(dyn);   // 8 ints
            __shared__ int schunkbase;
            int lane = tid & 31;
            int w    = tid >> 5;
            int nChunks = (N + 255) >> 8;
            for (int chunk = csrRank; chunk < nChunks; chunk += nCsr) {
                int i = chunk * 256 + tid;
                int v = (i < N) ? __ldcg(&g_deg[i]) : 0;
                if (i < N) g_dinv[i] = rsqrtf((float)(v + 1));   // +1: self loop
                int p = v;
#pragma unroll
                for (int off = 1; off < 32; off <<= 1) {
                    int tt = __shfl_up_sync(0xffffffffu, p, off);
                    if (lane >= off) p += tt;
                }
                if (lane == 31) swsum[w] = p;
                __syncthreads();
                if (tid == 0) {
                    int run = 0;
#pragma unroll
                    for (int k = 0; k < 8; k++) { int s = swsum[k]; swsum[k] = run; run += s; }
                    schunkbase = atomicAdd(&g_total, run);
                }
                __syncthreads();
                if (i < N) g_rowstart[i] = schunkbase + swsum[w] + p - v;
                __syncthreads();
            }
        }
        csr_barrier((unsigned)(3 * nCsr));

        // phase 3: scatter columns
        for (int e = gtid; e < E; e += Tcsr) {
            int r = ei[e];
            int c = ei[E + e];
            if (r != c) {
                int rs = __ldcg(&g_rowstart[r]);
                int sl = __ldcg(&g_slot[e]);
                g_col[rs + sl] = c;
            }
        }
    }

    // ---------- grid-wide barrier (one-wave grid) ----------
    __syncthreads();
    if (tid == 0) {
        __threadfence();
        atomicAdd(&g_gctr, 1u);
        while (ld_acq(&g_gctr) < (unsigned)nBlocks) __nanosleep(64);
    }
    __syncthreads();

    // ---------- scale phase: xwh[i,:] *= dinv[i] (all blocks) ----------
    {
        uint4* xh4 = reinterpret_cast<uint4*>(g_xwh);
        int gidx  = blockIdx.x * 256 + tid;
        int total = N * 8;
        int step  = nBlocks * 256;
        for (int idx = gidx; idx < total; idx += step) {
            int row = idx >> 3;
            float d = __ldcg(&g_dinv[row]);
            uint4 v = __ldcg(&xh4[idx]);
            __half2* h = reinterpret_cast<__half2*>(&v);
#pragma unroll
            for (int q = 0; q < 4; q++) {
                float2 f = __half22float2(h[q]);
                h[q] = __floats2half2_rn(d * f.x, d * f.y);
            }
            xh4[idx] = v;
        }
    }
}

// ---------------- aggregation: out[r] = dinv[r]*(xwh[r] + sum_c xwh[c]) ----------------
__device__ __forceinline__ void h8_add(uint4 v, float* acc) {
    const __half2* h = reinterpret_cast<const __half2*>(&v);
#pragma unroll
    for (int q = 0; q < 4; q++) {
        float2 f = __half22float2(h[q]);
        acc[2 * q]     += f.x;
        acc[2 * q + 1] += f.y;
    }
}

__global__ __launch_bounds__(256) void k_agg(float* __restrict__ out, int N) {
    // reset mega's counters for the next replay (no agg block reads them)
    if (blockIdx.x == 0 && threadIdx.x == 0) {
        g_barctr = 0u; g_gctr = 0u; g_total = 0; g_wt_ready = 0u;
    }

    int t   = blockIdx.x * blockDim.x + threadIdx.x;
    int row = t >> 3;          // 8 lanes per row
    int l   = t & 7;
    if (row >= N) return;

    const uint4* xh = reinterpret_cast<const uint4*>(g_xwh);
    float dr = g_dinv[row];

    float acc[8];
#pragma unroll
    for (int q = 0; q < 8; q++) acc[q] = 0.0f;
    h8_add(xh[(size_t)row * 8 + l], acc);   // self loop (already dinv[r]-scaled)

    int s0  = g_rowstart[row];
    int cnt = g_deg[row];

    int j = 0;
    for (; j + 4 <= cnt; j += 4) {
        int c0 = __ldg(&g_col[s0 + j]);
        int c1 = __ldg(&g_col[s0 + j + 1]);
        int c2 = __ldg(&g_col[s0 + j + 2]);
        int c3 = __ldg(&g_col[s0 + j + 3]);
        uint4 v0 = xh[(size_t)c0 * 8 + l];
        uint4 v1 = xh[(size_t)c1 * 8 + l];
        uint4 v2 = xh[(size_t)c2 * 8 + l];
        uint4 v3 = xh[(size_t)c3 * 8 + l];
        h8_add(v0, acc);
        h8_add(v1, acc);
        h8_add(v2, acc);
        h8_add(v3, acc);
    }
    for (; j < cnt; j++) {
        int c = __ldg(&g_col[s0 + j]);
        h8_add(xh[(size_t)c * 8 + l], acc);
    }

    float4 o0 = make_float4(dr * acc[0], dr * acc[1], dr * acc[2], dr * acc[3]);
    float4 o1 = make_float4(dr * acc[4], dr * acc[5], dr * acc[6], dr * acc[7]);
    float4* dst = reinterpret_cast<float4*>(out + (size_t)row * OUT_SIZE + l * 8);
    dst[0] = o0;
    dst[1] = o1;
}

// ---------------------------------------------------------------------------
extern "C" void kernel_launch(void* const* d_in, const int* in_sizes, int n_in,
                              void* d_out, int out_size) {
    const int*   ei = (const int*)d_in[0];     // [2, E]
    const float* x  = (const float*)d_in[1];   // [N, 256]
    const float* W  = (const float*)d_in[3];   // [64, 256]
    float* out = (float*)d_out;

    int E = in_sizes[0] / 2;
    int N = in_sizes[1] / IN_SIZE;

    cudaFuncSetAttribute(k_mega, cudaFuncAttributeMaxDynamicSharedMemorySize, GEMM_SMEM);

    int dev = 0;
    cudaGetDevice(&dev);
    int sms = 0;
    cudaDeviceGetAttribute(&sms, cudaDevAttrMultiProcessorCount, dev);
    int mb = 0;
    cudaOccupancyMaxActiveBlocksPerMultiprocessor(&mb, k_mega, 256, GEMM_SMEM);
    if (mb < 1) mb = 1;
    if (sms < 1) sms = 148;

    int nBlocks = sms * mb;                       // exactly one resident wave
    int tiles   = (N + GM - 1) / GM;
    int gemmB   = (nBlocks * 7) / 16;             // ~0.44 GEMM / 0.56 CSR
    if (gemmB < 1) gemmB = 1;
    if (gemmB > nBlocks - 1) gemmB = nBlocks - 1;
    int nCsr = nBlocks - gemmB;

    k_mega<<<nBlocks, 256, GEMM_SMEM>>>(ei, x, W, N, E, tiles, gemmB, nCsr, nBlocks);
    k_agg <<<(N * 8 + 255) / 256, 256>>>(out, N);
}